// round 1
// baseline (speedup 1.0000x reference)
#include <cuda_runtime.h>
#include <math.h>

#define NN 100000
#define NE 400000
#define NG 4096
#define DD 128
#define HH 256
#define NL 20
#define G_EPS 1e-7f
#define BN_EPS 1e-5f

// ---------------- scratch (device globals; no allocations) ----------------
__device__ float g_h [NN*DD];
__device__ float g_h2[NN*DD];
__device__ float g_hh[NN*DD];
__device__ float g_a1[NN*HH];
__device__ float g_a2[NN*HH];
__device__ double g_sum[HH];
__device__ double g_sumsq[HH];
__device__ int   g_deg[NN];
__device__ int   g_off[NN+1];
__device__ int   g_cursor[NN];
__device__ int   g_eid[NE];
__device__ int   g_partial[256];
__device__ float g_pool[NG];
__device__ int   g_cnt[NG];

#define SCAN_CHUNK 512
#define SCAN_NB ((NN + SCAN_CHUNK - 1) / SCAN_CHUNK)   // 196

// ---------------- small utility kernels ----------------
__global__ void k_zero_int(int* p, int n) {
    int i = blockIdx.x * blockDim.x + threadIdx.x;
    if (i < n) p[i] = 0;
}
__global__ void k_zero_float(float* p, int n) {
    int i = blockIdx.x * blockDim.x + threadIdx.x;
    if (i < n) p[i] = 0.f;
}
__global__ void k_zero_bn() {
    int i = threadIdx.x;
    g_sum[i] = 0.0; g_sumsq[i] = 0.0;
}

// ---------------- CSR build ----------------
__global__ void k_count_deg(const int* __restrict__ dst) {
    int e = blockIdx.x * blockDim.x + threadIdx.x;
    if (e < NE) atomicAdd(&g_deg[dst[e]], 1);
}
__global__ void k_scanA() {
    __shared__ int sm[SCAN_CHUNK];
    int tid = threadIdx.x;
    int gi = blockIdx.x * SCAN_CHUNK + tid;
    sm[tid] = (gi < NN) ? g_deg[gi] : 0;
    __syncthreads();
    for (int s = SCAN_CHUNK / 2; s > 0; s >>= 1) {
        if (tid < s) sm[tid] += sm[tid + s];
        __syncthreads();
    }
    if (tid == 0) g_partial[blockIdx.x] = sm[0];
}
__global__ void k_scanB() {
    __shared__ int sp[256];
    int tid = threadIdx.x;
    if (tid < SCAN_NB) sp[tid] = g_partial[tid];
    __syncthreads();
    if (tid == 0) {
        int run = 0;
        for (int i = 0; i < SCAN_NB; i++) { int v = sp[i]; sp[i] = run; run += v; }
        g_off[NN] = run;
    }
    __syncthreads();
    if (tid < SCAN_NB) g_partial[tid] = sp[tid];
}
__global__ void k_scanC() {
    __shared__ int sm[SCAN_CHUNK];
    int tid = threadIdx.x;
    int gi = blockIdx.x * SCAN_CHUNK + tid;
    int v = (gi < NN) ? g_deg[gi] : 0;
    sm[tid] = v;
    __syncthreads();
    // Hillis-Steele inclusive scan
    for (int o = 1; o < SCAN_CHUNK; o <<= 1) {
        int t = (tid >= o) ? sm[tid - o] : 0;
        __syncthreads();
        sm[tid] += t;
        __syncthreads();
    }
    if (gi < NN) g_off[gi] = sm[tid] - v + g_partial[blockIdx.x];
}
__global__ void k_fill(const int* __restrict__ dst) {
    int e = blockIdx.x * blockDim.x + threadIdx.x;
    if (e < NE) {
        int d = dst[e];
        int p = atomicAdd(&g_cursor[d], 1);
        g_eid[g_off[d] + p] = e;
    }
}

// ---------------- atom encoder ----------------
__global__ void k_atom(const int* __restrict__ x, const float* __restrict__ emb,
                       float* __restrict__ h) {
    int n = blockIdx.x;
    int d = threadIdx.x;
    float s = 0.f;
    #pragma unroll
    for (int i = 0; i < 9; i++) {
        int id = x[n * 9 + i];
        s += emb[((size_t)i * 119 + id) * DD + d];
    }
    h[(size_t)n * DD + d] = s;
}

// ---------------- message + scatter softmax (online, one pass) ----------------
__global__ void k_msg(const float* __restrict__ h, const int* __restrict__ src,
                      const int* __restrict__ ea, const float* __restrict__ bond,
                      const float* __restrict__ tptr, float* __restrict__ hh) {
    int n = blockIdx.x;
    int d = threadIdx.x;
    float tv = __ldg(tptr);
    int beg = g_off[n], end = g_off[n + 1];
    float mrun = -3.4e38f;
    float dsum = 0.f, nsum = 0.f;
    for (int j = beg; j < end; j++) {
        int e = g_eid[j];
        int s = src[e];
        int a0 = ea[e * 3 + 0], a1 = ea[e * 3 + 1], a2 = ea[e * 3 + 2];
        float m = h[(size_t)s * DD + d]
                + bond[(size_t)a0 * DD + d]
                + bond[(size_t)(6 + a1) * DD + d]
                + bond[(size_t)(12 + a2) * DD + d];
        m = fmaxf(m, 0.f) + G_EPS;
        float sc = m * tv;
        if (sc > mrun) {
            float corr = expf(mrun - sc);   // expf(-inf)=0 on first edge
            dsum *= corr; nsum *= corr; mrun = sc;
        }
        float ex = expf(sc - mrun);
        dsum += ex;
        nsum += m * ex;
    }
    float mo = (end > beg) ? (nsum / fmaxf(dsum, G_EPS)) : 0.f;
    hh[(size_t)n * DD + d] = h[(size_t)n * DD + d] + mo;
}

// ---------------- SGEMM: C = A[M,K] @ B[K,Nc] + bias (+resid) ----------------
__global__ __launch_bounds__(256) void k_sgemm(
    const float* __restrict__ A, const float* __restrict__ B,
    const float* __restrict__ bias, const float* __restrict__ resid,
    float* __restrict__ C, int M, int K, int Nc)
{
    const int BM = 128, BN = 128, BK = 8, TM = 8, TN = 8;
    __shared__ float As[BK][BM];
    __shared__ float Bs[BK][BN];
    int tid = threadIdx.x;
    int tr = tid / 16;           // 0..15
    int tc = tid % 16;           // 0..15
    int aRow0 = blockIdx.x * BM;
    int bCol0 = blockIdx.y * BN;

    float acc[TM][TN];
    #pragma unroll
    for (int i = 0; i < TM; i++)
        #pragma unroll
        for (int j = 0; j < TN; j++) acc[i][j] = 0.f;

    int ar = tid >> 1;
    int ac = (tid & 1) * 4;
    int brr = tid >> 5;
    int bcc = (tid & 31) * 4;

    for (int kt = 0; kt < K; kt += BK) {
        int garow = aRow0 + ar;
        float4 va = make_float4(0.f, 0.f, 0.f, 0.f);
        if (garow < M)
            va = *(const float4*)(A + (size_t)garow * K + kt + ac);
        As[ac + 0][ar] = va.x; As[ac + 1][ar] = va.y;
        As[ac + 2][ar] = va.z; As[ac + 3][ar] = va.w;

        float4 vb = *(const float4*)(B + (size_t)(kt + brr) * Nc + bCol0 + bcc);
        *(float4*)&Bs[brr][bcc] = vb;
        __syncthreads();

        #pragma unroll
        for (int k = 0; k < BK; k++) {
            float ra[TM], rb[TN];
            #pragma unroll
            for (int i = 0; i < TM; i++) ra[i] = As[k][tr * TM + i];
            #pragma unroll
            for (int j = 0; j < TN; j++) rb[j] = Bs[k][tc * TN + j];
            #pragma unroll
            for (int i = 0; i < TM; i++)
                #pragma unroll
                for (int j = 0; j < TN; j++)
                    acc[i][j] += ra[i] * rb[j];
        }
        __syncthreads();
    }

    #pragma unroll
    for (int i = 0; i < TM; i++) {
        int row = aRow0 + tr * TM + i;
        if (row < M) {
            #pragma unroll
            for (int j = 0; j < TN; j++) {
                int col = bCol0 + tc * TN + j;
                float v = acc[i][j] + bias[col];
                if (resid) v += resid[(size_t)row * Nc + col];
                C[(size_t)row * Nc + col] = v;
            }
        }
    }
}

// ---------------- BatchNorm ----------------
__global__ void k_bn_stats(const float* __restrict__ x, int M, int C) {
    int c = threadIdx.x;
    double s = 0.0, ss = 0.0;
    for (int r = blockIdx.x; r < M; r += gridDim.x) {
        float v = x[(size_t)r * C + c];
        s += v;
        ss += (double)v * (double)v;
    }
    atomicAdd(&g_sum[c], s);
    atomicAdd(&g_sumsq[c], ss);
}
__global__ void k_bn_apply(const float* __restrict__ x, float* __restrict__ y,
                           const float* __restrict__ gam, const float* __restrict__ bet,
                           int M, int C, int do_relu) {
    size_t idx = (size_t)blockIdx.x * blockDim.x + threadIdx.x;
    if (idx >= (size_t)M * C) return;
    int c = (int)(idx % C);
    double mu = g_sum[c] / M;
    double var = g_sumsq[c] / M - mu * mu;
    float rs = rsqrtf((float)var + BN_EPS);
    float v = (x[idx] - (float)mu) * rs * gam[c] + bet[c];
    if (do_relu) v = fmaxf(v, 0.f);
    y[idx] = v;
}

// ---------------- final BN + pool + linear ----------------
__global__ void k_pool(const float* __restrict__ h, const int* __restrict__ batch,
                       const float* __restrict__ predW,
                       const float* __restrict__ gam, const float* __restrict__ bet) {
    int g = blockIdx.x * blockDim.x + threadIdx.x;
    int node = g >> 5;
    int lane = g & 31;
    if (node >= NN) return;
    float acc = 0.f;
    #pragma unroll
    for (int d = lane; d < DD; d += 32) {
        double mu = g_sum[d] / NN;
        double var = g_sumsq[d] / NN - mu * mu;
        float rs = rsqrtf((float)var + BN_EPS);
        float v = (h[(size_t)node * DD + d] - (float)mu) * rs * gam[d] + bet[d];
        acc += v * predW[d];
    }
    #pragma unroll
    for (int o = 16; o > 0; o >>= 1) acc += __shfl_down_sync(0xffffffffu, acc, o);
    if (lane == 0) {
        int b = batch[node];
        atomicAdd(&g_pool[b], acc);
        atomicAdd(&g_cnt[b], 1);
    }
}
__global__ void k_finish(float* __restrict__ out, const float* __restrict__ predb) {
    int g = blockIdx.x * blockDim.x + threadIdx.x;
    if (g < NG) out[g] = g_pool[g] / fmaxf((float)g_cnt[g], 1.f) + predb[0];
}

// ---------------- host driver ----------------
template <typename T>
static T* symaddr(const void* sym) {
    void* p = nullptr;
    cudaGetSymbolAddress(&p, sym);
    return (T*)p;
}

extern "C" void kernel_launch(void* const* d_in, const int* in_sizes, int n_in,
                              void* d_out, int out_size) {
    const int*   x     = (const int*)d_in[0];
    const int*   ei    = (const int*)d_in[1];
    const int*   ea    = (const int*)d_in[2];
    const int*   batch = (const int*)d_in[3];
    const float* atom  = (const float*)d_in[4];
    const float* bond  = (const float*)d_in[5];
    const float* W1    = (const float*)d_in[6];
    const float* b1    = (const float*)d_in[7];
    const float* g1    = (const float*)d_in[8];
    const float* be1   = (const float*)d_in[9];
    const float* W2    = (const float*)d_in[10];
    const float* b2    = (const float*)d_in[11];
    const float* g2    = (const float*)d_in[12];
    const float* be2   = (const float*)d_in[13];
    const float* W3    = (const float*)d_in[14];
    const float* b3    = (const float*)d_in[15];
    const float* t     = (const float*)d_in[16];
    const float* ng    = (const float*)d_in[17];
    const float* nb    = (const float*)d_in[18];
    const float* predW = (const float*)d_in[19];
    const float* predb = (const float*)d_in[20];
    float* out = (float*)d_out;

    const int* src = ei;
    const int* dst = ei + NE;

    float* ph  = symaddr<float>(g_h);
    float* ph2 = symaddr<float>(g_h2);
    float* phh = symaddr<float>(g_hh);
    float* pa1 = symaddr<float>(g_a1);
    float* pa2 = symaddr<float>(g_a2);
    int*   pdeg    = symaddr<int>(g_deg);
    int*   pcursor = symaddr<int>(g_cursor);
    float* ppool   = symaddr<float>(g_pool);
    int*   pcnt    = symaddr<int>(g_cnt);

    // ---- CSR build ----
    k_zero_int<<<(NN + 255) / 256, 256>>>(pdeg, NN);
    k_zero_int<<<(NN + 255) / 256, 256>>>(pcursor, NN);
    k_count_deg<<<(NE + 255) / 256, 256>>>(dst);
    k_scanA<<<SCAN_NB, SCAN_CHUNK>>>();
    k_scanB<<<1, 256>>>();
    k_scanC<<<SCAN_NB, SCAN_CHUNK>>>();
    k_fill<<<(NE + 255) / 256, 256>>>(dst);

    // ---- atom encoder ----
    k_atom<<<NN, DD>>>(x, atom, ph);

    const int GM = (NN + 127) / 128;

    for (int l = 0; l < NL; l++) {
        const float* hin;
        if (l == 0) {
            hin = ph;
        } else {
            k_zero_bn<<<1, HH>>>();
            k_bn_stats<<<512, DD>>>(ph, NN, DD);
            k_bn_apply<<<(int)(((size_t)NN * DD + 255) / 256), 256>>>(
                ph, ph2, ng + (size_t)(l - 1) * DD, nb + (size_t)(l - 1) * DD, NN, DD, 1);
            hin = ph2;
        }

        k_msg<<<NN, DD>>>(hin, src, ea, bond + (size_t)l * 3 * 6 * DD, t + l, phh);

        // GEMM1: [N,128]x[128,256]
        k_sgemm<<<dim3(GM, HH / 128), 256>>>(phh, W1 + (size_t)l * DD * HH,
                                             b1 + (size_t)l * HH, nullptr, pa1, NN, DD, HH);
        k_zero_bn<<<1, HH>>>();
        k_bn_stats<<<512, HH>>>(pa1, NN, HH);
        k_bn_apply<<<(int)(((size_t)NN * HH + 255) / 256), 256>>>(
            pa1, pa1, g1 + (size_t)l * HH, be1 + (size_t)l * HH, NN, HH, 1);

        // GEMM2: [N,256]x[256,256]
        k_sgemm<<<dim3(GM, HH / 128), 256>>>(pa1, W2 + (size_t)l * HH * HH,
                                             b2 + (size_t)l * HH, nullptr, pa2, NN, HH, HH);
        k_zero_bn<<<1, HH>>>();
        k_bn_stats<<<512, HH>>>(pa2, NN, HH);
        k_bn_apply<<<(int)(((size_t)NN * HH + 255) / 256), 256>>>(
            pa2, pa2, g2 + (size_t)l * HH, be2 + (size_t)l * HH, NN, HH, 1);

        // GEMM3: [N,256]x[256,128] (+ residual for l>=1), writes h in place
        k_sgemm<<<dim3(GM, DD / 128), 256>>>(pa2, W3 + (size_t)l * HH * DD,
                                             b3 + (size_t)l * DD, (l > 0) ? ph : nullptr,
                                             ph, NN, HH, DD);
    }

    // ---- final BN + pool + prediction ----
    k_zero_bn<<<1, HH>>>();
    k_bn_stats<<<512, DD>>>(ph, NN, DD);
    k_zero_float<<<(NG + 255) / 256, 256>>>(ppool, NG);
    k_zero_int<<<(NG + 255) / 256, 256>>>(pcnt, NG);
    k_pool<<<(NN * 32 + 255) / 256, 256>>>(ph, batch, predW,
                                           ng + (size_t)(NL - 1) * DD,
                                           nb + (size_t)(NL - 1) * DD);
    k_finish<<<(NG + 255) / 256, 256>>>(out, predb);
}

// round 5
// speedup vs baseline: 1.2621x; 1.2621x over previous
#include <cuda_runtime.h>
#include <mma.h>
#include <math.h>

using namespace nvcuda;

#define NN 100000
#define MP 100096          // padded to 782*128
#define NE 400000
#define NG 4096
#define DD 128
#define HH 256
#define NL 20
#define G_EPS 1e-7f
#define BN_EPS 1e-5f

// ---------------- scratch (device globals; no allocations) ----------------
__device__ float g_h [MP*DD];
__device__ float g_h2[MP*DD];
__device__ float g_hh[MP*DD];
__device__ float g_a1[MP*HH];
__device__ float g_a2[MP*HH];
__device__ double g_sum[HH];
__device__ double g_sumsq[HH];
__device__ float g_mu[HH];
__device__ float g_rstd[HH];
__device__ int   g_deg[NN];
__device__ int   g_off[NN+1];
__device__ int   g_cursor[NN];
__device__ int   g_eid[NE];
__device__ int   g_partial[256];
__device__ float g_pool[NG];
__device__ int   g_cnt[NG];

#define SCAN_CHUNK 512
#define SCAN_NB ((NN + SCAN_CHUNK - 1) / SCAN_CHUNK)   // 196

// ---------------- small utility kernels ----------------
__global__ void k_init() {
    int i = blockIdx.x * blockDim.x + threadIdx.x;
    if (i < NN) { g_deg[i] = 0; g_cursor[i] = 0; }
    if (i < NG) { g_pool[i] = 0.f; g_cnt[i] = 0; }
}
__global__ void k_zero_bn() {
    int i = threadIdx.x;
    g_sum[i] = 0.0; g_sumsq[i] = 0.0;
}

// ---------------- CSR build ----------------
__global__ void k_count_deg(const int* __restrict__ dst) {
    int e = blockIdx.x * blockDim.x + threadIdx.x;
    if (e < NE) atomicAdd(&g_deg[dst[e]], 1);
}
__global__ void k_scanA() {
    __shared__ int sm[SCAN_CHUNK];
    int tid = threadIdx.x;
    int gi = blockIdx.x * SCAN_CHUNK + tid;
    sm[tid] = (gi < NN) ? g_deg[gi] : 0;
    __syncthreads();
    for (int s = SCAN_CHUNK / 2; s > 0; s >>= 1) {
        if (tid < s) sm[tid] += sm[tid + s];
        __syncthreads();
    }
    if (tid == 0) g_partial[blockIdx.x] = sm[0];
}
__global__ void k_scanB() {
    __shared__ int sp[256];
    int tid = threadIdx.x;
    if (tid < SCAN_NB) sp[tid] = g_partial[tid];
    __syncthreads();
    if (tid == 0) {
        int run = 0;
        for (int i = 0; i < SCAN_NB; i++) { int v = sp[i]; sp[i] = run; run += v; }
        g_off[NN] = run;
    }
    __syncthreads();
    if (tid < SCAN_NB) g_partial[tid] = sp[tid];
}
__global__ void k_scanC() {
    __shared__ int sm[SCAN_CHUNK];
    int tid = threadIdx.x;
    int gi = blockIdx.x * SCAN_CHUNK + tid;
    int v = (gi < NN) ? g_deg[gi] : 0;
    sm[tid] = v;
    __syncthreads();
    for (int o = 1; o < SCAN_CHUNK; o <<= 1) {
        int t = (tid >= o) ? sm[tid - o] : 0;
        __syncthreads();
        sm[tid] += t;
        __syncthreads();
    }
    if (gi < NN) g_off[gi] = sm[tid] - v + g_partial[blockIdx.x];
}
__global__ void k_fill(const int* __restrict__ dst) {
    int e = blockIdx.x * blockDim.x + threadIdx.x;
    if (e < NE) {
        int d = dst[e];
        int p = atomicAdd(&g_cursor[d], 1);
        g_eid[g_off[d] + p] = e;
    }
}

// ---------------- atom encoder ----------------
__global__ void k_atom(const int* __restrict__ x, const float* __restrict__ emb,
                       float* __restrict__ h) {
    int n = blockIdx.x;
    int d = threadIdx.x;
    float s = 0.f;
    #pragma unroll
    for (int i = 0; i < 9; i++) {
        int id = x[n * 9 + i];
        s += emb[((size_t)i * 119 + id) * DD + d];
    }
    h[(size_t)n * DD + d] = s;
}

// ---------------- message + scatter softmax (online, staged metadata) -------
__global__ void k_msg(const float* __restrict__ h, const int* __restrict__ src,
                      const int* __restrict__ ea, const float* __restrict__ bond,
                      const float* __restrict__ tptr, float* __restrict__ hh) {
    __shared__ int ssrc[128];
    __shared__ int spack[128];
    int n = blockIdx.x;
    int d = threadIdx.x;
    float tv = __ldg(tptr);
    int beg = g_off[n], end = g_off[n + 1];
    float mrun = -3.4e38f;
    float dsum = 0.f, nsum = 0.f;
    for (int base = beg; base < end; base += 128) {
        int j = base + d;
        if (j < end) {
            int e = g_eid[j];
            ssrc[d]  = src[e];
            spack[d] = ea[e * 3 + 0] | (ea[e * 3 + 1] << 8) | (ea[e * 3 + 2] << 16);
        }
        __syncthreads();
        int cnt = min(end - base, 128);
        for (int jj = 0; jj < cnt; jj++) {
            int s = ssrc[jj];
            int pk = spack[jj];
            int a0 = pk & 255, a1 = (pk >> 8) & 255, a2 = pk >> 16;
            float m = __ldg(&h[(size_t)s * DD + d])
                    + __ldg(&bond[(size_t)a0 * DD + d])
                    + __ldg(&bond[(size_t)(6 + a1) * DD + d])
                    + __ldg(&bond[(size_t)(12 + a2) * DD + d]);
            m = fmaxf(m, 0.f) + G_EPS;
            float sc = m * tv;
            if (sc > mrun) {
                float corr = __expf(mrun - sc);   // first edge: exp(-big)=0
                dsum *= corr; nsum *= corr; mrun = sc;
            }
            float ex = __expf(sc - mrun);
            dsum += ex;
            nsum += m * ex;
        }
        __syncthreads();
    }
    float mo = (end > beg) ? (nsum / fmaxf(dsum, G_EPS)) : 0.f;
    hh[(size_t)n * DD + d] = h[(size_t)n * DD + d] + mo;
}

// ------------- 3xTF32 WMMA GEMM: C = A[M,K]@B[K,Nc] (+resid) ---------------
// Split A,B into tf32 hi/lo; acc = Ah*Bh + Ah*Bl + Al*Bh (fp32 accumulate).
// M multiple of 128 (padded), K multiple of 16, Nc multiple of 128.
#define GBM 128
#define GBN 128
#define GBK 16
#define LDA (GBK + 8)     // 24
#define LDB (GBN + 8)     // 136

__global__ __launch_bounds__(256) void k_gemm_tf32x3(
    const float* __restrict__ A, const float* __restrict__ B,
    const float* __restrict__ resid, float* __restrict__ C,
    int K, int Nc)
{
    __shared__ float Ah[GBM][LDA];   // 12 KB
    __shared__ float Al[GBM][LDA];   // 12 KB
    __shared__ float Bh[GBK][LDB];   // 8.5 KB
    __shared__ float Bl[GBK][LDB];   // 8.5 KB
    int tid = threadIdx.x;
    int wid = tid >> 5;
    int wm = wid & 3;        // warp row 0..3  -> 32 rows each
    int wn = wid >> 2;       // warp col 0..1  -> 64 cols each
    int row0 = blockIdx.x * GBM;
    int col0 = blockIdx.y * GBN;

    wmma::fragment<wmma::accumulator, 16, 16, 8, float> cf[2][4];
    if (resid) {
        #pragma unroll
        for (int i = 0; i < 2; i++)
            #pragma unroll
            for (int j = 0; j < 4; j++)
                wmma::load_matrix_sync(cf[i][j],
                    resid + (size_t)(row0 + wm * 32 + i * 16) * Nc + col0 + wn * 64 + j * 16,
                    Nc, wmma::mem_row_major);
    } else {
        #pragma unroll
        for (int i = 0; i < 2; i++)
            #pragma unroll
            for (int j = 0; j < 4; j++)
                wmma::fill_fragment(cf[i][j], 0.f);
    }

    for (int kt = 0; kt < K; kt += GBK) {
        // stage A tile 128x16 (2 float4 per thread), split hi/lo
        #pragma unroll
        for (int i = 0; i < 2; i++) {
            int idx = tid + 256 * i;
            int r = idx >> 2, c = (idx & 3) * 4;
            float4 v = *(const float4*)(A + (size_t)(row0 + r) * K + kt + c);
            float hx = wmma::__float_to_tf32(v.x);
            float hy = wmma::__float_to_tf32(v.y);
            float hz = wmma::__float_to_tf32(v.z);
            float hw = wmma::__float_to_tf32(v.w);
            Ah[r][c + 0] = hx; Al[r][c + 0] = wmma::__float_to_tf32(v.x - hx);
            Ah[r][c + 1] = hy; Al[r][c + 1] = wmma::__float_to_tf32(v.y - hy);
            Ah[r][c + 2] = hz; Al[r][c + 2] = wmma::__float_to_tf32(v.z - hz);
            Ah[r][c + 3] = hw; Al[r][c + 3] = wmma::__float_to_tf32(v.w - hw);
        }
        // stage B tile 16x128 (2 float4 per thread), split hi/lo
        #pragma unroll
        for (int i = 0; i < 2; i++) {
            int idx = tid + 256 * i;
            int r = idx >> 5, c = (idx & 31) * 4;
            float4 v = *(const float4*)(B + (size_t)(kt + r) * Nc + col0 + c);
            float hx = wmma::__float_to_tf32(v.x);
            float hy = wmma::__float_to_tf32(v.y);
            float hz = wmma::__float_to_tf32(v.z);
            float hw = wmma::__float_to_tf32(v.w);
            Bh[r][c + 0] = hx; Bl[r][c + 0] = wmma::__float_to_tf32(v.x - hx);
            Bh[r][c + 1] = hy; Bl[r][c + 1] = wmma::__float_to_tf32(v.y - hy);
            Bh[r][c + 2] = hz; Bl[r][c + 2] = wmma::__float_to_tf32(v.z - hz);
            Bh[r][c + 3] = hw; Bl[r][c + 3] = wmma::__float_to_tf32(v.w - hw);
        }
        __syncthreads();

        #pragma unroll
        for (int ks = 0; ks < GBK / 8; ks++) {
            wmma::fragment<wmma::matrix_a, 16, 16, 8, wmma::precision::tf32, wmma::row_major> ah[2], al[2];
            wmma::fragment<wmma::matrix_b, 16, 16, 8, wmma::precision::tf32, wmma::row_major> bh[4], bl[4];
            #pragma unroll
            for (int i = 0; i < 2; i++) {
                wmma::load_matrix_sync(ah[i], &Ah[wm * 32 + i * 16][ks * 8], LDA);
                wmma::load_matrix_sync(al[i], &Al[wm * 32 + i * 16][ks * 8], LDA);
            }
            #pragma unroll
            for (int j = 0; j < 4; j++) {
                wmma::load_matrix_sync(bh[j], &Bh[ks * 8][wn * 64 + j * 16], LDB);
                wmma::load_matrix_sync(bl[j], &Bl[ks * 8][wn * 64 + j * 16], LDB);
            }
            #pragma unroll
            for (int i = 0; i < 2; i++)
                #pragma unroll
                for (int j = 0; j < 4; j++) {
                    wmma::mma_sync(cf[i][j], al[i], bh[j], cf[i][j]);
                    wmma::mma_sync(cf[i][j], ah[i], bl[j], cf[i][j]);
                    wmma::mma_sync(cf[i][j], ah[i], bh[j], cf[i][j]);
                }
        }
        __syncthreads();
    }

    #pragma unroll
    for (int i = 0; i < 2; i++)
        #pragma unroll
        for (int j = 0; j < 4; j++)
            wmma::store_matrix_sync(
                C + (size_t)(row0 + wm * 32 + i * 16) * Nc + col0 + wn * 64 + j * 16,
                cf[i][j], Nc, wmma::mem_row_major);
}

// ---------------- BatchNorm ----------------
__global__ void k_bn_stats(const float* __restrict__ x, int M, int C) {
    int c = threadIdx.x;
    double s = 0.0, ss = 0.0;
    for (int r = blockIdx.x; r < M; r += gridDim.x) {
        float v = x[(size_t)r * C + c];
        s += v;
        ss += (double)v * (double)v;
    }
    atomicAdd(&g_sum[c], s);
    atomicAdd(&g_sumsq[c], ss);
}
__global__ void k_bn_fin(int M, int C) {
    int c = threadIdx.x;
    if (c < C) {
        double mu = g_sum[c] / M;
        double var = g_sumsq[c] / M - mu * mu;
        g_mu[c] = (float)mu;
        g_rstd[c] = rsqrtf((float)var + BN_EPS);
    }
}
__global__ void k_bn_apply(const float4* __restrict__ x, float4* __restrict__ y,
                           const float4* __restrict__ gam, const float4* __restrict__ bet,
                           int M, int C4, int do_relu) {
    size_t idx = (size_t)blockIdx.x * blockDim.x + threadIdx.x;
    if (idx >= (size_t)M * C4) return;
    int c4 = (int)(idx % C4);
    float4 v = x[idx];
    float4 mu = ((const float4*)g_mu)[c4];
    float4 rs = ((const float4*)g_rstd)[c4];
    float4 g = __ldg(&gam[c4]);
    float4 b = __ldg(&bet[c4]);
    v.x = (v.x - mu.x) * rs.x * g.x + b.x;
    v.y = (v.y - mu.y) * rs.y * g.y + b.y;
    v.z = (v.z - mu.z) * rs.z * g.z + b.z;
    v.w = (v.w - mu.w) * rs.w * g.w + b.w;
    if (do_relu) {
        v.x = fmaxf(v.x, 0.f); v.y = fmaxf(v.y, 0.f);
        v.z = fmaxf(v.z, 0.f); v.w = fmaxf(v.w, 0.f);
    }
    y[idx] = v;
}

// ---------------- final BN + pool + linear ----------------
__global__ void k_pool(const float* __restrict__ h, const int* __restrict__ batch,
                       const float* __restrict__ predW,
                       const float* __restrict__ gam, const float* __restrict__ bet) {
    int g = blockIdx.x * blockDim.x + threadIdx.x;
    int node = g >> 5;
    int lane = g & 31;
    if (node >= NN) return;
    float acc = 0.f;
    #pragma unroll
    for (int d = lane; d < DD; d += 32) {
        float v = (h[(size_t)node * DD + d] - g_mu[d]) * g_rstd[d] * gam[d] + bet[d];
        acc += v * predW[d];
    }
    #pragma unroll
    for (int o = 16; o > 0; o >>= 1) acc += __shfl_down_sync(0xffffffffu, acc, o);
    if (lane == 0) {
        int b = batch[node];
        atomicAdd(&g_pool[b], acc);
        atomicAdd(&g_cnt[b], 1);
    }
}
__global__ void k_finish(float* __restrict__ out, const float* __restrict__ predb) {
    int g = blockIdx.x * blockDim.x + threadIdx.x;
    if (g < NG) out[g] = g_pool[g] / fmaxf((float)g_cnt[g], 1.f) + predb[0];
}

// ---------------- host driver ----------------
template <typename T>
static T* symaddr(const void* sym) {
    void* p = nullptr;
    cudaGetSymbolAddress(&p, sym);
    return (T*)p;
}

extern "C" void kernel_launch(void* const* d_in, const int* in_sizes, int n_in,
                              void* d_out, int out_size) {
    const int*   x     = (const int*)d_in[0];
    const int*   ei    = (const int*)d_in[1];
    const int*   ea    = (const int*)d_in[2];
    const int*   batch = (const int*)d_in[3];
    const float* atom  = (const float*)d_in[4];
    const float* bond  = (const float*)d_in[5];
    const float* W1    = (const float*)d_in[6];
    // b1 = d_in[7] : cancelled by BatchNorm (per-channel constant)
    const float* g1    = (const float*)d_in[8];
    const float* be1   = (const float*)d_in[9];
    const float* W2    = (const float*)d_in[10];
    // b2 = d_in[11] : cancelled by BatchNorm
    const float* g2    = (const float*)d_in[12];
    const float* be2   = (const float*)d_in[13];
    const float* W3    = (const float*)d_in[14];
    // b3 = d_in[15] : only enters the residual stream; cancelled at every BN
    const float* t     = (const float*)d_in[16];
    const float* ng    = (const float*)d_in[17];
    const float* nb    = (const float*)d_in[18];
    const float* predW = (const float*)d_in[19];
    const float* predb = (const float*)d_in[20];
    float* out = (float*)d_out;

    const int* src = ei;
    const int* dst = ei + NE;

    float* ph  = symaddr<float>(g_h);
    float* ph2 = symaddr<float>(g_h2);
    float* phh = symaddr<float>(g_hh);
    float* pa1 = symaddr<float>(g_a1);
    float* pa2 = symaddr<float>(g_a2);

    // ---- init + CSR build ----
    k_init<<<(NN + 255) / 256, 256>>>();
    k_count_deg<<<(NE + 255) / 256, 256>>>(dst);
    k_scanA<<<SCAN_NB, SCAN_CHUNK>>>();
    k_scanB<<<1, 256>>>();
    k_scanC<<<SCAN_NB, SCAN_CHUNK>>>();
    k_fill<<<(NE + 255) / 256, 256>>>(dst);

    // ---- atom encoder ----
    k_atom<<<NN, DD>>>(x, atom, ph);

    const int GM = MP / 128;   // 782

    for (int l = 0; l < NL; l++) {
        const float* hin;
        if (l == 0) {
            hin = ph;
        } else {
            k_zero_bn<<<1, HH>>>();
            k_bn_stats<<<512, DD>>>(ph, NN, DD);
            k_bn_fin<<<1, HH>>>(NN, DD);
            k_bn_apply<<<(int)(((size_t)NN * (DD/4) + 255) / 256), 256>>>(
                (const float4*)ph, (float4*)ph2,
                (const float4*)(ng + (size_t)(l - 1) * DD),
                (const float4*)(nb + (size_t)(l - 1) * DD), NN, DD/4, 1);
            hin = ph2;
        }

        k_msg<<<NN, DD>>>(hin, src, ea, bond + (size_t)l * 3 * 6 * DD, t + l, phh);

        // GEMM1: [MP,128]x[128,256]
        k_gemm_tf32x3<<<dim3(GM, HH / 128), 256>>>(phh, W1 + (size_t)l * DD * HH,
                                                   nullptr, pa1, DD, HH);
        k_zero_bn<<<1, HH>>>();
        k_bn_stats<<<512, HH>>>(pa1, NN, HH);
        k_bn_fin<<<1, HH>>>(NN, HH);
        k_bn_apply<<<(int)(((size_t)NN * (HH/4) + 255) / 256), 256>>>(
            (const float4*)pa1, (float4*)pa1,
            (const float4*)(g1 + (size_t)l * HH),
            (const float4*)(be1 + (size_t)l * HH), NN, HH/4, 1);

        // GEMM2: [MP,256]x[256,256]
        k_gemm_tf32x3<<<dim3(GM, HH / 128), 256>>>(pa1, W2 + (size_t)l * HH * HH,
                                                   nullptr, pa2, HH, HH);
        k_zero_bn<<<1, HH>>>();
        k_bn_stats<<<512, HH>>>(pa2, NN, HH);
        k_bn_fin<<<1, HH>>>(NN, HH);
        k_bn_apply<<<(int)(((size_t)NN * (HH/4) + 255) / 256), 256>>>(
            (const float4*)pa2, (float4*)pa2,
            (const float4*)(g2 + (size_t)l * HH),
            (const float4*)(be2 + (size_t)l * HH), NN, HH/4, 1);

        // GEMM3: [MP,256]x[256,128] (+ residual for l>=1), writes h in place
        k_gemm_tf32x3<<<dim3(GM, DD / 128), 256>>>(pa2, W3 + (size_t)l * HH * DD,
                                                   (l > 0) ? ph : nullptr, ph, HH, DD);
    }

    // ---- final BN + pool + prediction ----
    k_zero_bn<<<1, HH>>>();
    k_bn_stats<<<512, DD>>>(ph, NN, DD);
    k_bn_fin<<<1, HH>>>(NN, DD);
    k_pool<<<(NN * 32 + 255) / 256, 256>>>(ph, batch, predW,
                                           ng + (size_t)(NL - 1) * DD,
                                           nb + (size_t)(NL - 1) * DD);
    k_finish<<<(NG + 255) / 256, 256>>>(out, predb);
}

// round 9
// speedup vs baseline: 2.3402x; 1.8542x over previous
#include <cuda_runtime.h>
#include <cstdint>
#include <mma.h>
#include <math.h>

using namespace nvcuda;

#define NN 100000
#define MP 100096          // padded to 782*128
#define NE 400000
#define NG 4096
#define DD 128
#define HH 256
#define NL 20
#define G_EPS 1e-7f
#define BN_EPS 1e-5f

// ---------------- scratch (device globals; no allocations) ----------------
__device__ float g_h [MP*DD];
__device__ float g_h2[MP*DD];
__device__ float g_hh[MP*DD];
__device__ float g_a1[MP*HH];
__device__ float g_a2[MP*HH];
__device__ double g_sum[HH];
__device__ double g_sumsq[HH];
__device__ float g_mu[HH];
__device__ float g_rstd[HH];
__device__ int   g_deg[NN];
__device__ int   g_off[NN+1];
__device__ int   g_cursor[NN];
__device__ int   g_eid[NE];
__device__ int   g_partial[256];
__device__ float g_pool[NG];
__device__ int   g_cnt[NG];

#define SCAN_CHUNK 512
#define SCAN_NB ((NN + SCAN_CHUNK - 1) / SCAN_CHUNK)   // 196

// ---------------- small utility kernels ----------------
__global__ void k_init() {
    int i = blockIdx.x * blockDim.x + threadIdx.x;
    if (i < NN) { g_deg[i] = 0; g_cursor[i] = 0; }
    if (i < NG) { g_pool[i] = 0.f; g_cnt[i] = 0; }
}
__global__ void k_zero_bn() {
    int i = threadIdx.x;
    g_sum[i] = 0.0; g_sumsq[i] = 0.0;
}

// ---------------- CSR build ----------------
__global__ void k_count_deg(const int* __restrict__ dst) {
    int e = blockIdx.x * blockDim.x + threadIdx.x;
    if (e < NE) atomicAdd(&g_deg[dst[e]], 1);
}
__global__ void k_scanA() {
    __shared__ int sm[SCAN_CHUNK];
    int tid = threadIdx.x;
    int gi = blockIdx.x * SCAN_CHUNK + tid;
    sm[tid] = (gi < NN) ? g_deg[gi] : 0;
    __syncthreads();
    for (int s = SCAN_CHUNK / 2; s > 0; s >>= 1) {
        if (tid < s) sm[tid] += sm[tid + s];
        __syncthreads();
    }
    if (tid == 0) g_partial[blockIdx.x] = sm[0];
}
__global__ void k_scanB() {
    __shared__ int sp[256];
    int tid = threadIdx.x;
    if (tid < SCAN_NB) sp[tid] = g_partial[tid];
    __syncthreads();
    if (tid == 0) {
        int run = 0;
        for (int i = 0; i < SCAN_NB; i++) { int v = sp[i]; sp[i] = run; run += v; }
        g_off[NN] = run;
    }
    __syncthreads();
    if (tid < SCAN_NB) g_partial[tid] = sp[tid];
}
__global__ void k_scanC() {
    __shared__ int sm[SCAN_CHUNK];
    int tid = threadIdx.x;
    int gi = blockIdx.x * SCAN_CHUNK + tid;
    int v = (gi < NN) ? g_deg[gi] : 0;
    sm[tid] = v;
    __syncthreads();
    for (int o = 1; o < SCAN_CHUNK; o <<= 1) {
        int t = (tid >= o) ? sm[tid - o] : 0;
        __syncthreads();
        sm[tid] += t;
        __syncthreads();
    }
    if (gi < NN) g_off[gi] = sm[tid] - v + g_partial[blockIdx.x];
}
__global__ void k_fill(const int* __restrict__ dst) {
    int e = blockIdx.x * blockDim.x + threadIdx.x;
    if (e < NE) {
        int d = dst[e];
        int p = atomicAdd(&g_cursor[d], 1);
        g_eid[g_off[d] + p] = e;
    }
}

// ---------------- atom encoder ----------------
__global__ void k_atom(const int* __restrict__ x, const float* __restrict__ emb,
                       float* __restrict__ h) {
    int n = blockIdx.x;
    int d = threadIdx.x;
    float s = 0.f;
    #pragma unroll
    for (int i = 0; i < 9; i++) {
        int id = x[n * 9 + i];
        s += emb[((size_t)i * 119 + id) * DD + d];
    }
    h[(size_t)n * DD + d] = s;
}

// ---------------- message + scatter softmax (online, staged metadata) -------
__global__ void k_msg(const float* __restrict__ h, const int* __restrict__ src,
                      const int* __restrict__ ea, const float* __restrict__ bond,
                      const float* __restrict__ tptr, float* __restrict__ hh) {
    __shared__ int ssrc[128];
    __shared__ int spack[128];
    int n = blockIdx.x;
    int d = threadIdx.x;
    float tv = __ldg(tptr);
    int beg = g_off[n], end = g_off[n + 1];
    float mrun = -3.4e38f;
    float dsum = 0.f, nsum = 0.f;
    for (int base = beg; base < end; base += 128) {
        int j = base + d;
        if (j < end) {
            int e = g_eid[j];
            ssrc[d]  = src[e];
            spack[d] = ea[e * 3 + 0] | (ea[e * 3 + 1] << 8) | (ea[e * 3 + 2] << 16);
        }
        __syncthreads();
        int cnt = min(end - base, 128);
        for (int jj = 0; jj < cnt; jj++) {
            int s = ssrc[jj];
            int pk = spack[jj];
            int a0 = pk & 255, a1 = (pk >> 8) & 255, a2 = pk >> 16;
            float m = __ldg(&h[(size_t)s * DD + d])
                    + __ldg(&bond[(size_t)a0 * DD + d])
                    + __ldg(&bond[(size_t)(6 + a1) * DD + d])
                    + __ldg(&bond[(size_t)(12 + a2) * DD + d]);
            m = fmaxf(m, 0.f) + G_EPS;
            float sc = m * tv;
            if (sc > mrun) {
                float corr = __expf(mrun - sc);   // first edge: exp(-big)=0
                dsum *= corr; nsum *= corr; mrun = sc;
            }
            float ex = __expf(sc - mrun);
            dsum += ex;
            nsum += m * ex;
        }
        __syncthreads();
    }
    float mo = (end > beg) ? (nsum / fmaxf(dsum, G_EPS)) : 0.f;
    hh[(size_t)n * DD + d] = h[(size_t)n * DD + d] + mo;
}

// ---------------- cp.async helpers ----------------
__device__ __forceinline__ void cp_async16(void* smem, const void* gmem) {
    unsigned int s = (unsigned int)__cvta_generic_to_shared(smem);
    asm volatile("cp.async.ca.shared.global [%0], [%1], 16;\n" :: "r"(s), "l"(gmem));
}
__device__ __forceinline__ void cp_commit() {
    asm volatile("cp.async.commit_group;\n");
}
template <int N>
__device__ __forceinline__ void cp_wait() {
    asm volatile("cp.async.wait_group %0;\n" :: "n"(N));
}

// ------------- 3xTF32 WMMA GEMM, cp.async double-buffered -------------------
// C = A[M,K]@B[K,Nc] (+resid).  Register-level hi/lo split (3 MMA terms).
// M multiple of 128 (padded), K multiple of 32, Nc multiple of 128.
#define GBK 32
#define LDA 36            // 32 + 4 pad   (row stride bytes = 144, 16B aligned)
#define LDB 132           // 128 + 4 pad  (row stride bytes = 528, 16B aligned)
#define SMEM_GEMM ((2*128*LDA + 2*GBK*LDB) * 4)   // 70656 bytes

__global__ __launch_bounds__(256) void k_gemm_tf32x3(
    const float* __restrict__ A, const float* __restrict__ B,
    const float* __restrict__ resid, float* __restrict__ C,
    int K, int Nc)
{
    extern __shared__ float dsm[];
    float (*As)[128][LDA] = (float(*)[128][LDA])dsm;
    float (*Bs)[GBK][LDB] = (float(*)[GBK][LDB])(dsm + 2 * 128 * LDA);

    int tid = threadIdx.x;
    int wid = tid >> 5;
    int wm = wid & 3;        // warp row 0..3  -> 32 rows each
    int wn = wid >> 2;       // warp col 0..1  -> 64 cols each
    int row0 = blockIdx.x * 128;
    int col0 = blockIdx.y * 128;

    wmma::fragment<wmma::accumulator, 16, 16, 8, float> cf[2][4];
    if (resid) {
        #pragma unroll
        for (int i = 0; i < 2; i++)
            #pragma unroll
            for (int j = 0; j < 4; j++)
                wmma::load_matrix_sync(cf[i][j],
                    resid + (size_t)(row0 + wm * 32 + i * 16) * Nc + col0 + wn * 64 + j * 16,
                    Nc, wmma::mem_row_major);
    } else {
        #pragma unroll
        for (int i = 0; i < 2; i++)
            #pragma unroll
            for (int j = 0; j < 4; j++)
                wmma::fill_fragment(cf[i][j], 0.f);
    }

    const int nk = K / GBK;

    // async stage loader: A 128x32 (4x16B/thread), B 32x128 (4x16B/thread)
    auto stage = [&](int st, int kt) {
        #pragma unroll
        for (int i = 0; i < 4; i++) {
            int idx = tid + 256 * i;
            int r = idx >> 3, c = (idx & 7) * 4;
            cp_async16(&As[st][r][c], A + (size_t)(row0 + r) * K + kt + c);
        }
        #pragma unroll
        for (int i = 0; i < 4; i++) {
            int idx = tid + 256 * i;
            int r = idx >> 5, c = (idx & 31) * 4;
            cp_async16(&Bs[st][r][c], B + (size_t)(kt + r) * Nc + col0 + c);
        }
        cp_commit();
    };

    stage(0, 0);

    for (int kt = 0; kt < nk; kt++) {
        if (kt + 1 < nk) {
            stage((kt + 1) & 1, (kt + 1) * GBK);
            cp_wait<1>();
        } else {
            cp_wait<0>();
        }
        __syncthreads();
        int st = kt & 1;

        #pragma unroll
        for (int ks = 0; ks < GBK / 8; ks++) {
            wmma::fragment<wmma::matrix_a, 16, 16, 8, wmma::precision::tf32, wmma::row_major> ah[2], al[2];
            wmma::fragment<wmma::matrix_b, 16, 16, 8, wmma::precision::tf32, wmma::row_major> bh[4], bl[4];
            #pragma unroll
            for (int i = 0; i < 2; i++) {
                wmma::load_matrix_sync(ah[i], &As[st][wm * 32 + i * 16][ks * 8], LDA);
                #pragma unroll
                for (int e = 0; e < ah[i].num_elements; e++) {
                    float v = ah[i].x[e];
                    float hi = wmma::__float_to_tf32(v);
                    ah[i].x[e] = hi;
                    al[i].x[e] = wmma::__float_to_tf32(v - hi);
                }
            }
            #pragma unroll
            for (int j = 0; j < 4; j++) {
                wmma::load_matrix_sync(bh[j], &Bs[st][ks * 8][wn * 64 + j * 16], LDB);
                #pragma unroll
                for (int e = 0; e < bh[j].num_elements; e++) {
                    float v = bh[j].x[e];
                    float hi = wmma::__float_to_tf32(v);
                    bh[j].x[e] = hi;
                    bl[j].x[e] = wmma::__float_to_tf32(v - hi);
                }
            }
            #pragma unroll
            for (int i = 0; i < 2; i++)
                #pragma unroll
                for (int j = 0; j < 4; j++) {
                    wmma::mma_sync(cf[i][j], al[i], bh[j], cf[i][j]);
                    wmma::mma_sync(cf[i][j], ah[i], bl[j], cf[i][j]);
                    wmma::mma_sync(cf[i][j], ah[i], bh[j], cf[i][j]);
                }
        }
        __syncthreads();
    }

    #pragma unroll
    for (int i = 0; i < 2; i++)
        #pragma unroll
        for (int j = 0; j < 4; j++)
            wmma::store_matrix_sync(
                C + (size_t)(row0 + wm * 32 + i * 16) * Nc + col0 + wn * 64 + j * 16,
                cf[i][j], Nc, wmma::mem_row_major);
}

// ---------------- BatchNorm ----------------
__global__ void k_bn_stats(const float* __restrict__ x, int M, int C) {
    int c = threadIdx.x;
    double s = 0.0, ss = 0.0;
    for (int r = blockIdx.x; r < M; r += gridDim.x) {
        float v = x[(size_t)r * C + c];
        s += v;
        ss += (double)v * (double)v;
    }
    atomicAdd(&g_sum[c], s);
    atomicAdd(&g_sumsq[c], ss);
}
__global__ void k_bn_fin(int M, int C) {
    int c = threadIdx.x;
    if (c < C) {
        double mu = g_sum[c] / M;
        double var = g_sumsq[c] / M - mu * mu;
        g_mu[c] = (float)mu;
        g_rstd[c] = rsqrtf((float)var + BN_EPS);
    }
}
__global__ void k_bn_apply(const float4* __restrict__ x, float4* __restrict__ y,
                           const float4* __restrict__ gam, const float4* __restrict__ bet,
                           int M, int C4, int do_relu) {
    size_t idx = (size_t)blockIdx.x * blockDim.x + threadIdx.x;
    if (idx >= (size_t)M * C4) return;
    int c4 = (int)(idx % C4);
    float4 v = x[idx];
    float4 mu = ((const float4*)g_mu)[c4];
    float4 rs = ((const float4*)g_rstd)[c4];
    float4 g = __ldg(&gam[c4]);
    float4 b = __ldg(&bet[c4]);
    v.x = (v.x - mu.x) * rs.x * g.x + b.x;
    v.y = (v.y - mu.y) * rs.y * g.y + b.y;
    v.z = (v.z - mu.z) * rs.z * g.z + b.z;
    v.w = (v.w - mu.w) * rs.w * g.w + b.w;
    if (do_relu) {
        v.x = fmaxf(v.x, 0.f); v.y = fmaxf(v.y, 0.f);
        v.z = fmaxf(v.z, 0.f); v.w = fmaxf(v.w, 0.f);
    }
    y[idx] = v;
}

// ---------------- final BN + pool + linear ----------------
__global__ void k_pool(const float* __restrict__ h, const int* __restrict__ batch,
                       const float* __restrict__ predW,
                       const float* __restrict__ gam, const float* __restrict__ bet) {
    int g = blockIdx.x * blockDim.x + threadIdx.x;
    int node = g >> 5;
    int lane = g & 31;
    if (node >= NN) return;
    float acc = 0.f;
    #pragma unroll
    for (int d = lane; d < DD; d += 32) {
        float v = (h[(size_t)node * DD + d] - g_mu[d]) * g_rstd[d] * gam[d] + bet[d];
        acc += v * predW[d];
    }
    #pragma unroll
    for (int o = 16; o > 0; o >>= 1) acc += __shfl_down_sync(0xffffffffu, acc, o);
    if (lane == 0) {
        int b = batch[node];
        atomicAdd(&g_pool[b], acc);
        atomicAdd(&g_cnt[b], 1);
    }
}
__global__ void k_finish(float* __restrict__ out, const float* __restrict__ predb) {
    int g = blockIdx.x * blockDim.x + threadIdx.x;
    if (g < NG) out[g] = g_pool[g] / fmaxf((float)g_cnt[g], 1.f) + predb[0];
}

// ---------------- host driver ----------------
template <typename T>
static T* symaddr(const void* sym) {
    void* p = nullptr;
    cudaGetSymbolAddress(&p, sym);
    return (T*)p;
}

extern "C" void kernel_launch(void* const* d_in, const int* in_sizes, int n_in,
                              void* d_out, int out_size) {
    const int*   x     = (const int*)d_in[0];
    const int*   ei    = (const int*)d_in[1];
    const int*   ea    = (const int*)d_in[2];
    const int*   batch = (const int*)d_in[3];
    const float* atom  = (const float*)d_in[4];
    const float* bond  = (const float*)d_in[5];
    const float* W1    = (const float*)d_in[6];
    // b1 = d_in[7] : cancelled by BatchNorm (per-channel constant)
    const float* g1    = (const float*)d_in[8];
    const float* be1   = (const float*)d_in[9];
    const float* W2    = (const float*)d_in[10];
    // b2 = d_in[11] : cancelled by BatchNorm
    const float* g2    = (const float*)d_in[12];
    const float* be2   = (const float*)d_in[13];
    const float* W3    = (const float*)d_in[14];
    // b3 = d_in[15] : only enters the residual stream; cancelled at every BN
    const float* t     = (const float*)d_in[16];
    const float* ng    = (const float*)d_in[17];
    const float* nb    = (const float*)d_in[18];
    const float* predW = (const float*)d_in[19];
    const float* predb = (const float*)d_in[20];
    float* out = (float*)d_out;

    const int* src = ei;
    const int* dst = ei + NE;

    float* ph  = symaddr<float>(g_h);
    float* ph2 = symaddr<float>(g_h2);
    float* phh = symaddr<float>(g_hh);
    float* pa1 = symaddr<float>(g_a1);
    float* pa2 = symaddr<float>(g_a2);

    cudaFuncSetAttribute(k_gemm_tf32x3,
                         cudaFuncAttributeMaxDynamicSharedMemorySize, SMEM_GEMM);

    // ---- init + CSR build ----
    k_init<<<(NN + 255) / 256, 256>>>();
    k_count_deg<<<(NE + 255) / 256, 256>>>(dst);
    k_scanA<<<SCAN_NB, SCAN_CHUNK>>>();
    k_scanB<<<1, 256>>>();
    k_scanC<<<SCAN_NB, SCAN_CHUNK>>>();
    k_fill<<<(NE + 255) / 256, 256>>>(dst);

    // ---- atom encoder ----
    k_atom<<<NN, DD>>>(x, atom, ph);

    const int GM = MP / 128;   // 782

    for (int l = 0; l < NL; l++) {
        const float* hin;
        if (l == 0) {
            hin = ph;
        } else {
            k_zero_bn<<<1, HH>>>();
            k_bn_stats<<<512, DD>>>(ph, NN, DD);
            k_bn_fin<<<1, HH>>>(NN, DD);
            k_bn_apply<<<(int)(((size_t)NN * (DD/4) + 255) / 256), 256>>>(
                (const float4*)ph, (float4*)ph2,
                (const float4*)(ng + (size_t)(l - 1) * DD),
                (const float4*)(nb + (size_t)(l - 1) * DD), NN, DD/4, 1);
            hin = ph2;
        }

        k_msg<<<NN, DD>>>(hin, src, ea, bond + (size_t)l * 3 * 6 * DD, t + l, phh);

        // GEMM1: [MP,128]x[128,256]
        k_gemm_tf32x3<<<dim3(GM, HH / 128), 256, SMEM_GEMM>>>(
            phh, W1 + (size_t)l * DD * HH, nullptr, pa1, DD, HH);
        k_zero_bn<<<1, HH>>>();
        k_bn_stats<<<512, HH>>>(pa1, NN, HH);
        k_bn_fin<<<1, HH>>>(NN, HH);
        k_bn_apply<<<(int)(((size_t)NN * (HH/4) + 255) / 256), 256>>>(
            (const float4*)pa1, (float4*)pa1,
            (const float4*)(g1 + (size_t)l * HH),
            (const float4*)(be1 + (size_t)l * HH), NN, HH/4, 1);

        // GEMM2: [MP,256]x[256,256]
        k_gemm_tf32x3<<<dim3(GM, HH / 128), 256, SMEM_GEMM>>>(
            pa1, W2 + (size_t)l * HH * HH, nullptr, pa2, HH, HH);
        k_zero_bn<<<1, HH>>>();
        k_bn_stats<<<512, HH>>>(pa2, NN, HH);
        k_bn_fin<<<1, HH>>>(NN, HH);
        k_bn_apply<<<(int)(((size_t)NN * (HH/4) + 255) / 256), 256>>>(
            (const float4*)pa2, (float4*)pa2,
            (const float4*)(g2 + (size_t)l * HH),
            (const float4*)(be2 + (size_t)l * HH), NN, HH/4, 1);

        // GEMM3: [MP,256]x[256,128] (+ residual for l>=1), writes h in place
        k_gemm_tf32x3<<<dim3(GM, DD / 128), 256, SMEM_GEMM>>>(
            pa2, W3 + (size_t)l * HH * DD, (l > 0) ? ph : nullptr, ph, HH, DD);
    }

    // ---- final BN + pool + prediction ----
    k_zero_bn<<<1, HH>>>();
    k_bn_stats<<<512, DD>>>(ph, NN, DD);
    k_bn_fin<<<1, HH>>>(NN, DD);
    k_pool<<<(NN * 32 + 255) / 256, 256>>>(ph, batch, predW,
                                           ng + (size_t)(NL - 1) * DD,
                                           nb + (size_t)(NL - 1) * DD);
    k_finish<<<(NG + 255) / 256, 256>>>(out, predb);
}